// round 11
// baseline (speedup 1.0000x reference)
#include <cuda_runtime.h>
#include <cuda_bf16.h>
#include <stdint.h>
#include <math.h>

#define BATCH 4
#define SEQ   2048
#define DIN   1024
#define DD    64
#define MTOT  (BATCH * SEQ)
#define S_SPLIT 4
#define NEGF  -1e30f

// ---------------------------------------------------------------------------
// Device scratch (no cudaMalloc allowed)
// ---------------------------------------------------------------------------
__device__ float g_Q[MTOT * DD];
__device__ float g_K[MTOT * DD];
__device__ float g_V[MTOT * DD];
__device__ uint32_t g_hQ[MTOT * 32], g_lQ[MTOT * 32];
__device__ uint32_t g_hK[MTOT * 32], g_lK[MTOT * 32];
__device__ uint32_t g_hV[MTOT * 32], g_lV[MTOT * 32];
__device__ float g_pacc[S_SPLIT * MTOT * DD];
__device__ float g_pm[S_SPLIT * MTOT];
__device__ float g_pl[S_SPLIT * MTOT];

// ---------------------------------------------------------------------------
// Host-side replication of np.random.default_rng(0) mask-index generation
// ---------------------------------------------------------------------------
struct u128h { uint64_t hi, lo; };

static inline uint64_t mulhi64_h(uint64_t a, uint64_t b) {
  uint64_t al = (uint32_t)a, ah = a >> 32, bl = (uint32_t)b, bh = b >> 32;
  uint64_t p0 = al * bl, p1 = al * bh, p2 = ah * bl, p3 = ah * bh;
  uint64_t mid = (p0 >> 32) + (uint32_t)p1 + (uint32_t)p2;
  return p3 + (p1 >> 32) + (p2 >> 32) + (mid >> 32);
}

struct PCG64H {
  u128h state, inc;
  int has_uint32;
  uint32_t uinteger;
};

static inline void pcg_step_h(PCG64H* p) {
  const uint64_t mhi = 2549297995355413924ULL, mlo = 4865540595714422341ULL;
  u128h s = p->state, r;
  r.lo = s.lo * mlo;
  r.hi = mulhi64_h(s.lo, mlo) + s.lo * mhi + s.hi * mlo;
  uint64_t lo = r.lo + p->inc.lo;
  r.hi += p->inc.hi + (lo < r.lo);
  r.lo = lo;
  p->state = r;
}

static inline uint64_t rotr64_h(uint64_t v, unsigned r) {
  r &= 63u;
  return r ? ((v >> r) | (v << (64 - r))) : v;
}

static inline uint64_t pcg_next64_h(PCG64H* p) {
  pcg_step_h(p);
  return rotr64_h(p->state.hi ^ p->state.lo, (unsigned)(p->state.hi >> 58));
}

static inline uint32_t pcg_next32_h(PCG64H* p) {
  if (p->has_uint32) { p->has_uint32 = 0; return p->uinteger; }
  uint64_t n = pcg_next64_h(p);
  p->has_uint32 = 1;
  p->uinteger = (uint32_t)(n >> 32);
  return (uint32_t)n;
}

static void seedseq0_state_h(uint64_t out[4]) {
  const uint32_t INIT_A = 0x43b0d7e5u, MULT_A = 0x931e8875u;
  const uint32_t INIT_B = 0x8b51f9ddu, MULT_B = 0x58f38dedu;
  const uint32_t MIX_L = 0xca01f9ddu, MIX_R = 0x4973f715u;
  uint32_t pool[4];
  uint32_t hc = INIT_A;
  for (int i = 0; i < 4; i++) {
    uint32_t v = 0u;
    v ^= hc; hc *= MULT_A; v *= hc; v ^= v >> 16;
    pool[i] = v;
  }
  for (int s = 0; s < 4; s++) {
    for (int d = 0; d < 4; d++) {
      if (s == d) continue;
      uint32_t v = pool[s];
      v ^= hc; hc *= MULT_A; v *= hc; v ^= v >> 16;
      uint32_t r = (pool[d] * MIX_L) ^ (v * MIX_R);
      r ^= r >> 16;
      pool[d] = r;
    }
  }
  uint32_t hcb = INIT_B;
  uint32_t st[8];
  for (int i = 0; i < 8; i++) {
    uint32_t dv = pool[i & 3];
    dv ^= hcb; hcb *= MULT_B; dv *= hcb; dv ^= dv >> 16;
    st[i] = dv;
  }
  for (int k2 = 0; k2 < 4; k2++)
    out[k2] = (uint64_t)st[2 * k2] | ((uint64_t)st[2 * k2 + 1] << 32);
}

static inline uint64_t lemire32_h(PCG64H* p, uint32_t rng) {
  if (rng == 0) return 0;
  const uint32_t rng_excl = rng + 1;
  uint64_t m = (uint64_t)pcg_next32_h(p) * (uint64_t)rng_excl;
  uint32_t leftover = (uint32_t)m;
  if (leftover < rng_excl) {
    const uint32_t threshold = (uint32_t)(0xFFFFFFFFu - rng) % rng_excl;
    while (leftover < threshold) {
      m = (uint64_t)pcg_next32_h(p) * (uint64_t)rng_excl;
      leftover = (uint32_t)m;
    }
  }
  return m >> 32;
}

static void choice3_2048_h(PCG64H* p, int64_t idx[3]) {
  const int size = 3, pop = 2048;
  const uint64_t mask = 3;
  uint64_t hset[4] = {~0ull, ~0ull, ~0ull, ~0ull};
  for (int j = pop - size; j < pop; j++) {
    uint64_t val = lemire32_h(p, (uint32_t)j);
    uint64_t loc = val & mask;
    while (hset[loc] != ~0ull && hset[loc] != val) loc = (loc + 1) & mask;
    if (hset[loc] == ~0ull) {
      hset[loc] = val;
      idx[j - pop + size] = (int64_t)val;
    } else {
      loc = (uint64_t)j & mask;
      while (hset[loc] != ~0ull) loc = (loc + 1) & mask;
      hset[loc] = (uint64_t)j;
      idx[j - pop + size] = (int64_t)j;
    }
  }
  for (int i = size - 1; i >= 1; i--) {
    uint64_t jj = lemire32_h(p, (uint32_t)i);
    if ((int)jj != i) {
      int64_t t = idx[i]; idx[i] = idx[(int)jj]; idx[(int)jj] = t;
    }
  }
}

static void compute_mask_pairs_h(int gr[3], int gc[3]) {
  uint64_t sd[4];
  seedseq0_state_h(sd);
  PCG64H rng;
  rng.inc.hi = (sd[2] << 1) | (sd[3] >> 63);
  rng.inc.lo = (sd[3] << 1) | 1ull;
  rng.state.hi = 0; rng.state.lo = 0;
  pcg_step_h(&rng);
  uint64_t lo = rng.state.lo + sd[1];
  rng.state.hi += sd[0] + (lo < rng.state.lo);
  rng.state.lo = lo;
  pcg_step_h(&rng);
  rng.has_uint32 = 0; rng.uinteger = 0;

  int64_t rows[3], cols[3];
  choice3_2048_h(&rng, rows);
  choice3_2048_h(&rng, cols);
  for (int i = 0; i < 3; i++) { gr[i] = (int)rows[i]; gc[i] = (int)cols[i]; }
}

// ---------------------------------------------------------------------------
// helpers
// ---------------------------------------------------------------------------
__device__ __forceinline__ void split2(float x, float y, uint32_t& hi,
                                       uint32_t& lo) {
  float hx = __bfloat162float(__float2bfloat16(x));
  float hy = __bfloat162float(__float2bfloat16(y));
  __nv_bfloat162 h2 = __floats2bfloat162_rn(x, y);
  __nv_bfloat162 l2 = __floats2bfloat162_rn(x - hx, y - hy);
  hi = *reinterpret_cast<uint32_t*>(&h2);
  lo = *reinterpret_cast<uint32_t*>(&l2);
}

__device__ __forceinline__ uint32_t smem_u32(const void* p) {
  return (uint32_t)__cvta_generic_to_shared(p);
}

__device__ __forceinline__ void cp_async16(uint32_t saddr, const void* g) {
  asm volatile("cp.async.cg.shared.global [%0], [%1], 16;" ::"r"(saddr),
               "l"(g));
}
__device__ __forceinline__ void cp_commit() {
  asm volatile("cp.async.commit_group;");
}
template <int N>
__device__ __forceinline__ void cp_wait() {
  asm volatile("cp.async.wait_group %0;" ::"n"(N));
}

__device__ __forceinline__ void ldsm_x4(uint32_t& r0, uint32_t& r1,
                                        uint32_t& r2, uint32_t& r3,
                                        uint32_t addr) {
  asm volatile(
      "ldmatrix.sync.aligned.m8n8.x4.shared.b16 {%0,%1,%2,%3}, [%4];"
      : "=r"(r0), "=r"(r1), "=r"(r2), "=r"(r3)
      : "r"(addr));
}

__device__ __forceinline__ void ldsm_x4_t(uint32_t& r0, uint32_t& r1,
                                          uint32_t& r2, uint32_t& r3,
                                          uint32_t addr) {
  asm volatile(
      "ldmatrix.sync.aligned.m8n8.x4.trans.shared.b16 {%0,%1,%2,%3}, [%4];"
      : "=r"(r0), "=r"(r1), "=r"(r2), "=r"(r3)
      : "r"(addr));
}

__device__ __forceinline__ void mma_bf16(float& d0, float& d1, float& d2,
                                         float& d3, uint32_t a0, uint32_t a1,
                                         uint32_t a2, uint32_t a3, uint32_t b0,
                                         uint32_t b1) {
  asm volatile(
      "mma.sync.aligned.m16n8k16.row.col.f32.bf16.bf16.f32 "
      "{%0,%1,%2,%3},{%4,%5,%6,%7},{%8,%9},{%0,%1,%2,%3};"
      : "+f"(d0), "+f"(d1), "+f"(d2), "+f"(d3)
      : "r"(a0), "r"(a1), "r"(a2), "r"(a3), "r"(b0), "r"(b1));
}

// ---------------------------------------------------------------------------
// Projection GEMM, 3xBF16 m16n8k16, cp.async double-buffered raw staging
// (no register prefetch -> regs < 128 -> 4 CTAs/SM). No split-K.
// Epilogue writes fp32 + bf16 hi/lo planes.
// ---------------------------------------------------------------------------
#define PSTR 20
#define WSTR 36

__global__ __launch_bounds__(128, 4) void proj_kernel(
    const float* __restrict__ in_q, const float* __restrict__ in_k,
    const float* __restrict__ in_v,
    const float* __restrict__ Wq, const float* __restrict__ bq,
    const float* __restrict__ Wk, const float* __restrict__ bk,
    const float* __restrict__ Wv, const float* __restrict__ bv) {
  const float* A; const float* W; const float* bias; float* out;
  uint32_t* hP; uint32_t* lP;
  int z = blockIdx.y;
  if (z == 0)      { A = in_q; W = Wq; bias = bq; out = g_Q; hP = g_hQ; lP = g_lQ; }
  else if (z == 1) { A = in_k; W = Wk; bias = bk; out = g_K; hP = g_hK; lP = g_lK; }
  else             { A = in_v; W = Wv; bias = bv; out = g_V; hP = g_hV; lP = g_lV; }

  __shared__ float4 Araw[2][512];   // 64 rows x 8 float4, 8 KB x2
  __shared__ float4 Wraw[2][512];   // 32 rows x 16 float4, 8 KB x2
  __shared__ uint32_t Ah[64 * PSTR], Al[64 * PSTR];
  __shared__ uint32_t Wh[32 * WSTR], Wl[32 * WSTR];

  const int t = threadIdx.x;
  const int w = t >> 5;
  const int lane = t & 31;
  const int g = lane >> 2;
  const int tig = lane & 3;
  const int m0 = blockIdx.x * 64;
  const int mw = w * 16;

  float acc[8][4];
#pragma unroll
  for (int nb = 0; nb < 8; nb++)
#pragma unroll
    for (int i = 0; i < 4; i++) acc[nb][i] = 0.f;

  // issue chunk 0
#pragma unroll
  for (int i = 0; i < 4; i++) {
    int fidx = t + i * 128;
    cp_async16(smem_u32(&Araw[0][fidx]),
               &A[(size_t)(m0 + (fidx >> 3)) * DIN + (fidx & 7) * 4]);
    cp_async16(smem_u32(&Wraw[0][fidx]),
               &W[(size_t)(fidx >> 4) * DD + (fidx & 15) * 4]);
  }
  cp_commit();

  for (int c = 0; c < 32; c++) {
    if (c < 31) {
      int kc = (c + 1) * 32;
      int bufn = (c + 1) & 1;
#pragma unroll
      for (int i = 0; i < 4; i++) {
        int fidx = t + i * 128;
        cp_async16(smem_u32(&Araw[bufn][fidx]),
                   &A[(size_t)(m0 + (fidx >> 3)) * DIN + kc + (fidx & 7) * 4]);
        cp_async16(smem_u32(&Wraw[bufn][fidx]),
                   &W[(size_t)(kc + (fidx >> 4)) * DD + (fidx & 15) * 4]);
      }
      cp_commit();
      cp_wait<1>();
    } else {
      cp_wait<0>();
    }
    __syncthreads();  // chunk c staged; prior MMA done with Ah/Wh

    const float4* Ar = Araw[c & 1];
    const float4* Wr = Wraw[c & 1];
#pragma unroll
    for (int i = 0; i < 4; i++) {
      int fidx = t + i * 128;
      {
        float4 v = Ar[fidx];
        int row = fidx >> 3, cc = fidx & 7;
        uint32_t h0, l0, h1, l1;
        split2(v.x, v.y, h0, l0);
        split2(v.z, v.w, h1, l1);
        *(uint2*)&Ah[row * PSTR + 2 * cc] = make_uint2(h0, h1);
        *(uint2*)&Al[row * PSTR + 2 * cc] = make_uint2(l0, l1);
      }
      {
        float4 v = Wr[fidx];
        int krow = fidx >> 4, c4 = fidx & 15;
        uint32_t h0, l0, h1, l1;
        split2(v.x, v.y, h0, l0);
        split2(v.z, v.w, h1, l1);
        *(uint2*)&Wh[krow * WSTR + 2 * c4] = make_uint2(h0, h1);
        *(uint2*)&Wl[krow * WSTR + 2 * c4] = make_uint2(l0, l1);
      }
    }
    __syncthreads();

#pragma unroll
    for (int ks = 0; ks < 2; ks++) {
      int arow = mw + ((lane >> 3) & 1) * 8 + (lane & 7);
      int acol = ks * 8 + (lane >> 4) * 4;
      uint32_t ah0, ah1, ah2, ah3, al0, al1, al2, al3;
      ldsm_x4(ah0, ah1, ah2, ah3, smem_u32(&Ah[arow * PSTR + acol]));
      ldsm_x4(al0, al1, al2, al3, smem_u32(&Al[arow * PSTR + acol]));
#pragma unroll
      for (int nbp = 0; nbp < 4; nbp++) {
        int wk = ks * 16 + ((lane >> 3) & 1) * 8 + (lane & 7);
        int wnp = nbp * 8 + (lane >> 4) * 4;
        uint32_t bh0, bh1, bh2, bh3, bl0, bl1, bl2, bl3;
        ldsm_x4_t(bh0, bh1, bh2, bh3, smem_u32(&Wh[wk * WSTR + wnp]));
        ldsm_x4_t(bl0, bl1, bl2, bl3, smem_u32(&Wl[wk * WSTR + wnp]));
        int n0 = 2 * nbp, n1 = n0 + 1;
        mma_bf16(acc[n0][0], acc[n0][1], acc[n0][2], acc[n0][3],
                 ah0, ah1, ah2, ah3, bh0, bh1);
        mma_bf16(acc[n1][0], acc[n1][1], acc[n1][2], acc[n1][3],
                 ah0, ah1, ah2, ah3, bh2, bh3);
        mma_bf16(acc[n0][0], acc[n0][1], acc[n0][2], acc[n0][3],
                 al0, al1, al2, al3, bh0, bh1);
        mma_bf16(acc[n1][0], acc[n1][1], acc[n1][2], acc[n1][3],
                 al0, al1, al2, al3, bh2, bh3);
        mma_bf16(acc[n0][0], acc[n0][1], acc[n0][2], acc[n0][3],
                 ah0, ah1, ah2, ah3, bl0, bl1);
        mma_bf16(acc[n1][0], acc[n1][1], acc[n1][2], acc[n1][3],
                 ah0, ah1, ah2, ah3, bl2, bl3);
      }
    }
    __syncthreads();
  }

#pragma unroll
  for (int nb = 0; nb < 8; nb++) {
    int n = nb * 8 + tig * 2;
    float b0v = bias[n], b1v = bias[n + 1];
    float2 o0 = make_float2(acc[nb][0] + b0v, acc[nb][1] + b1v);
    float2 o1 = make_float2(acc[nb][2] + b0v, acc[nb][3] + b1v);
    size_t row0 = (size_t)(m0 + mw + g);
    size_t row1 = row0 + 8;
    *(float2*)&out[row0 * DD + n] = o0;
    *(float2*)&out[row1 * DD + n] = o1;
    uint32_t h, l;
    split2(o0.x, o0.y, h, l);
    hP[row0 * 32 + nb * 4 + tig] = h;
    lP[row0 * 32 + nb * 4 + tig] = l;
    split2(o1.x, o1.y, h, l);
    hP[row1 * 32 + nb * 4 + tig] = h;
    lP[row1 * 32 + nb * 4 + tig] = l;
  }
}

// ---------------------------------------------------------------------------
// Flash attention, 3xBF16 m16n8k16, split-K x4, cp.async plane staging,
// double-buffered.  (unchanged from R10)
// ---------------------------------------------------------------------------
#define KSTR 36
#define TILEW (64 * KSTR)

__global__ __launch_bounds__(128, 3) void attn_split_kernel() {
  extern __shared__ uint32_t sm[];
  uint32_t* KhB = sm;
  uint32_t* KlB = sm + 2 * TILEW;
  uint32_t* VhB = sm + 4 * TILEW;
  uint32_t* VlB = sm + 6 * TILEW;

  const int bid = blockIdx.x;
  const int s = bid >> 7;
  const int rest = bid & 127;
  const int b = rest >> 5;
  const int qt = rest & 31;
  const int qr0 = qt * 64;
  const int T = qt + 1;
  const int t0 = (s * T) / S_SPLIT;
  const int t1 = ((s + 1) * T) / S_SPLIT;

  const int t = threadIdx.x;
  const int w = t >> 5;
  const int lane = t & 31;
  const int g = lane >> 2;
  const int tig = lane & 3;
  const int mw = w * 16;

  const size_t pbase = ((size_t)s * BATCH + b) * SEQ + qr0;

  if (t0 == t1) {
    for (int i = t; i < 64 * 16; i += 128) {
      int row = i >> 4, c4 = (i & 15) * 4;
      *(float4*)&g_pacc[(pbase + row) * DD + c4] =
          make_float4(0.f, 0.f, 0.f, 0.f);
    }
    if (t < 64) { g_pm[pbase + t] = NEGF; g_pl[pbase + t] = 0.f; }
    return;
  }

  const uint32_t* __restrict__ pQh = g_hQ + (size_t)b * SEQ * 32;
  const uint32_t* __restrict__ pQl = g_lQ + (size_t)b * SEQ * 32;
  const uint32_t* __restrict__ pKh = g_hK + (size_t)b * SEQ * 32;
  const uint32_t* __restrict__ pKl = g_lK + (size_t)b * SEQ * 32;
  const uint32_t* __restrict__ pVh = g_hV + (size_t)b * SEQ * 32;
  const uint32_t* __restrict__ pVl = g_lV + (size_t)b * SEQ * 32;

#pragma unroll
  for (int i = 0; i < 4; i++) {
    int idx = t + i * 128;
    int row = idx >> 3, j4 = idx & 7;
    cp_async16(smem_u32(&KhB[row * KSTR + 4 * j4]),
               &pQh[(size_t)(qr0 + row) * 32 + 4 * j4]);
    cp_async16(smem_u32(&KlB[row * KSTR + 4 * j4]),
               &pQl[(size_t)(qr0 + row) * 32 + 4 * j4]);
  }
  cp_commit();
  cp_wait<0>();
  __syncthreads();

  uint32_t qh[4][4], ql[4][4];
#pragma unroll
  for (int ks = 0; ks < 4; ks++) {
    int arow = mw + ((lane >> 3) & 1) * 8 + (lane & 7);
    int acol = ks * 8 + (lane >> 4) * 4;
    ldsm_x4(qh[ks][0], qh[ks][1], qh[ks][2], qh[ks][3],
            smem_u32(&KhB[arow * KSTR + acol]));
    ldsm_x4(ql[ks][0], ql[ks][1], ql[ks][2], ql[ks][3],
            smem_u32(&KlB[arow * KSTR + acol]));
  }
  __syncthreads();

  {
    int j0 = t0 * 64;
#pragma unroll
    for (int i = 0; i < 4; i++) {
      int idx = t + i * 128;
      int row = idx >> 3, j4 = idx & 7;
      size_t goff = (size_t)(j0 + row) * 32 + 4 * j4;
      uint32_t soff = row * KSTR + 4 * j4;
      cp_async16(smem_u32(&KhB[soff]), &pKh[goff]);
      cp_async16(smem_u32(&KlB[soff]), &pKl[goff]);
      cp_async16(smem_u32(&VhB[soff]), &pVh[goff]);
      cp_async16(smem_u32(&VlB[soff]), &pVl[goff]);
    }
    cp_commit();
  }

  float m0 = NEGF, m1 = NEGF, l0s = 0.f, l1s = 0.f;
  float acc[8][4];
#pragma unroll
  for (int nb = 0; nb < 8; nb++)
#pragma unroll
    for (int i = 0; i < 4; i++) acc[nb][i] = 0.f;

  const int row0g = qr0 + mw + g;
  const int row1g = row0g + 8;

  for (int kt = t0; kt < t1; kt++) {
    const int it = kt - t0;
    const int p = it & 1;
    cp_wait<0>();
    __syncthreads();

    if (kt + 1 < t1) {
      int j0n = (kt + 1) * 64;
      uint32_t bofs = (p ^ 1) * TILEW;
#pragma unroll
      for (int i = 0; i < 4; i++) {
        int idx = t + i * 128;
        int row = idx >> 3, j4 = idx & 7;
        size_t goff = (size_t)(j0n + row) * 32 + 4 * j4;
        uint32_t soff = bofs + row * KSTR + 4 * j4;
        cp_async16(smem_u32(&KhB[soff]), &pKh[goff]);
        cp_async16(smem_u32(&KlB[soff]), &pKl[goff]);
        cp_async16(smem_u32(&VhB[soff]), &pVh[goff]);
        cp_async16(smem_u32(&VlB[soff]), &pVl[goff]);
      }
      cp_commit();
    }

    const uint32_t* KhT = KhB + p * TILEW;
    const uint32_t* KlT = KlB + p * TILEW;
    const uint32_t* VhT = VhB + p * TILEW;
    const uint32_t* VlT = VlB + p * TILEW;
    const int j0 = kt * 64;

    float sacc[8][4];
#pragma unroll
    for (int nb = 0; nb < 8; nb++)
#pragma unroll
      for (int i = 0; i < 4; i++) sacc[nb][i] = 0.f;
#pragma unroll
    for (int ks = 0; ks < 4; ks++) {
#pragma unroll
      for (int nbp = 0; nbp < 4; nbp++) {
        int krow = nbp * 16 + (lane >> 4) * 8 + (lane & 7);
        int kcol = ks * 8 + ((lane >> 3) & 1) * 4;
        uint32_t bh0, bh1, bh2, bh3, bl0, bl1, bl2, bl3;
        ldsm_x4(bh0, bh1, bh2, bh3, smem_u32(&KhT[krow * KSTR + kcol]));
        ldsm_x4(bl0, bl1, bl2, bl3, smem_u32(&KlT[krow * KSTR + kcol]));
        int n0 = 2 * nbp, n1 = n0 + 1;
        mma_bf16(sacc[n0][0], sacc[n0][1], sacc[n0][2], sacc[n0][3],
                 qh[ks][0], qh[ks][1], qh[ks][2], qh[ks][3], bh0, bh1);
        mma_bf16(sacc[n1][0], sacc[n1][1], sacc[n1][2], sacc[n1][3],
                 qh[ks][0], qh[ks][1], qh[ks][2], qh[ks][3], bh2, bh3);
        mma_bf16(sacc[n0][0], sacc[n0][1], sacc[n0][2], sacc[n0][3],
                 ql[ks][0], ql[ks][1], ql[ks][2], ql[ks][3], bh0, bh1);
        mma_bf16(sacc[n1][0], sacc[n1][1], sacc[n1][2], sacc[n1][3],
                 ql[ks][0], ql[ks][1], ql[ks][2], ql[ks][3], bh2, bh3);
        mma_bf16(sacc[n0][0], sacc[n0][1], sacc[n0][2], sacc[n0][3],
                 qh[ks][0], qh[ks][1], qh[ks][2], qh[ks][3], bl0, bl1);
        mma_bf16(sacc[n1][0], sacc[n1][1], sacc[n1][2], sacc[n1][3],
                 qh[ks][0], qh[ks][1], qh[ks][2], qh[ks][3], bl2, bl3);
      }
    }

#pragma unroll
    for (int nb = 0; nb < 8; nb++) {
      sacc[nb][0] *= 0.125f; sacc[nb][1] *= 0.125f;
      sacc[nb][2] *= 0.125f; sacc[nb][3] *= 0.125f;
    }

    if (kt == T - 1) {
#pragma unroll
      for (int nb = 0; nb < 8; nb++) {
        int kg = j0 + nb * 8 + tig * 2;
        if (kg > row0g)     sacc[nb][0] = NEGF;
        if (kg + 1 > row0g) sacc[nb][1] = NEGF;
        if (kg > row1g)     sacc[nb][2] = NEGF;
        if (kg + 1 > row1g) sacc[nb][3] = NEGF;
      }
    }

    float mx0 = NEGF, mx1 = NEGF;
#pragma unroll
    for (int nb = 0; nb < 8; nb++) {
      mx0 = fmaxf(mx0, fmaxf(sacc[nb][0], sacc[nb][1]));
      mx1 = fmaxf(mx1, fmaxf(sacc[nb][2], sacc[nb][3]));
    }
    mx0 = fmaxf(mx0, __shfl_xor_sync(0xffffffffu, mx0, 1));
    mx0 = fmaxf(mx0, __shfl_xor_sync(0xffffffffu, mx0, 2));
    mx1 = fmaxf(mx1, __shfl_xor_sync(0xffffffffu, mx1, 1));
    mx1 = fmaxf(mx1, __shfl_xor_sync(0xffffffffu, mx1, 2));
    const float mn0 = fmaxf(m0, mx0);
    const float mn1 = fmaxf(m1, mx1);
    const float c0 = __expf(m0 - mn0);
    const float c1 = __expf(m1 - mn1);

    uint32_t pha[8], phb[8], pla[8], plb[8];
    float s0 = 0.f, s1 = 0.f;
#pragma unroll
    for (int nb = 0; nb < 8; nb++) {
      float p00 = __expf(sacc[nb][0] - mn0);
      float p01 = __expf(sacc[nb][1] - mn0);
      float p10 = __expf(sacc[nb][2] - mn1);
      float p11 = __expf(sacc[nb][3] - mn1);
      s0 += p00 + p01;
      s1 += p10 + p11;
      split2(p00, p01, pha[nb], pla[nb]);
      split2(p10, p11, phb[nb], plb[nb]);
    }
    s0 += __shfl_xor_sync(0xffffffffu, s0, 1);
    s0 += __shfl_xor_sync(0xffffffffu, s0, 2);
    s1 += __shfl_xor_sync(0xffffffffu, s1, 1);
    s1 += __shfl_xor_sync(0xffffffffu, s1, 2);
    l0s = l0s * c0 + s0;
    l1s = l1s * c1 + s1;
    m0 = mn0;
    m1 = mn1;
#pragma unroll
    for (int nb = 0; nb < 8; nb++) {
      acc[nb][0] *= c0; acc[nb][1] *= c0;
      acc[nb][2] *= c1; acc[nb][3] *= c1;
    }

#pragma unroll
    for (int kb = 0; kb < 4; kb++) {
      uint32_t a0h = pha[2 * kb], a1h = phb[2 * kb];
      uint32_t a2h = pha[2 * kb + 1], a3h = phb[2 * kb + 1];
      uint32_t a0l = pla[2 * kb], a1l = plb[2 * kb];
      uint32_t a2l = pla[2 * kb + 1], a3l = plb[2 * kb + 1];
#pragma unroll
      for (int nbp = 0; nbp < 4; nbp++) {
        int vkey = kb * 16 + ((lane >> 3) & 1) * 8 + (lane & 7);
        int vdp = nbp * 8 + (lane >> 4) * 4;
        uint32_t bh0, bh1, bh2, bh3, bl0, bl1, bl2, bl3;
        ldsm_x4_t(bh0, bh1, bh2, bh3, smem_u32(&VhT[vkey * KSTR + vdp]));
        ldsm_x4_t(bl0, bl1, bl2, bl3, smem_u32(&VlT[vkey * KSTR + vdp]));
        int n0 = 2 * nbp, n1 = n0 + 1;
        mma_bf16(acc[n0][0], acc[n0][1], acc[n0][2], acc[n0][3],
                 a0h, a1h, a2h, a3h, bh0, bh1);
        mma_bf16(acc[n1][0], acc[n1][1], acc[n1][2], acc[n1][3],
                 a0h, a1h, a2h, a3h, bh2, bh3);
        mma_bf16(acc[n0][0], acc[n0][1], acc[n0][2], acc[n0][3],
                 a0l, a1l, a2l, a3l, bh0, bh1);
        mma_bf16(acc[n1][0], acc[n1][1], acc[n1][2], acc[n1][3],
                 a0l, a1l, a2l, a3l, bh2, bh3);
        mma_bf16(acc[n0][0], acc[n0][1], acc[n0][2], acc[n0][3],
                 a0h, a1h, a2h, a3h, bl0, bl1);
        mma_bf16(acc[n1][0], acc[n1][1], acc[n1][2], acc[n1][3],
                 a0h, a1h, a2h, a3h, bl2, bl3);
      }
    }
  }

  const size_t r0 = pbase + mw + g;
  const size_t r1 = r0 + 8;
  if (tig == 0) {
    g_pm[r0] = m0; g_pl[r0] = l0s;
    g_pm[r1] = m1; g_pl[r1] = l1s;
  }
#pragma unroll
  for (int nb = 0; nb < 8; nb++) {
    int n = nb * 8 + tig * 2;
    *(float2*)&g_pacc[r0 * DD + n] = make_float2(acc[nb][0], acc[nb][1]);
    *(float2*)&g_pacc[r1 * DD + n] = make_float2(acc[nb][2], acc[nb][3]);
  }
}

// ---------------------------------------------------------------------------
// Combine: 1024 blocks x 64 threads (8 rows/block) — latency-bound before,
// so 4x the block parallelism.
// ---------------------------------------------------------------------------
__global__ __launch_bounds__(64) void combine_kernel(
    float* __restrict__ out,
    int gr0, int gc0, int gr1, int gc1, int gr2, int gc2) {
  const int bid = blockIdx.x;
  const int b = bid >> 8;
  const int rt = bid & 255;
  const int t = threadIdx.x;
  const int r = t >> 3;
  const int sub = t & 7;
  const int row = rt * 8 + r;
  const int d0a = sub * 4;
  const int d0b = 32 + sub * 4;
  const size_t browoff = (size_t)b * SEQ + row;

  float ms[S_SPLIT], ls[S_SPLIT];
  float M = NEGF;
#pragma unroll
  for (int s = 0; s < S_SPLIT; s++) {
    size_t prow = ((size_t)s * BATCH + b) * SEQ + row;
    ms[s] = g_pm[prow];
    ls[s] = g_pl[prow];
    M = fmaxf(M, ms[s]);
  }
  float L = 0.f;
  float4 Aa = make_float4(0.f, 0.f, 0.f, 0.f);
  float4 Ab = make_float4(0.f, 0.f, 0.f, 0.f);
#pragma unroll
  for (int s = 0; s < S_SPLIT; s++) {
    size_t prow = ((size_t)s * BATCH + b) * SEQ + row;
    float w = __expf(ms[s] - M);
    L += ls[s] * w;
    const float* pr = g_pacc + prow * DD;
    float4 pa = *(const float4*)&pr[d0a];
    float4 pb = *(const float4*)&pr[d0b];
    Aa.x += w * pa.x; Aa.y += w * pa.y; Aa.z += w * pa.z; Aa.w += w * pa.w;
    Ab.x += w * pb.x; Ab.y += w * pb.y; Ab.z += w * pb.z; Ab.w += w * pb.w;
  }

  const int grs[3] = {gr0, gr1, gr2};
  const int gcs[3] = {gc0, gc1, gc2};
  const float* __restrict__ Qrow = g_Q + browoff * DD;
#pragma unroll
  for (int g = 0; g < 3; g++) {
    int grr = grs[g], gcc = gcs[g];
    if (row == grr && gcc > grr) {
      const float* Kg = g_K + ((size_t)b * SEQ + gcc) * DD;
      const float* Vg = g_V + ((size_t)b * SEQ + gcc) * DD;
      float part = 0.f;
#pragma unroll
      for (int i = 0; i < 4; i++) {
        part += Qrow[d0a + i] * Kg[d0a + i];
        part += Qrow[d0b + i] * Kg[d0b + i];
      }
      part += __shfl_xor_sync(0xffffffffu, part, 1);
      part += __shfl_xor_sync(0xffffffffu, part, 2);
      part += __shfl_xor_sync(0xffffffffu, part, 4);
      float sg = part * 0.125f;
      float mn = fmaxf(M, sg);
      float cw = __expf(M - mn);
      float pg = __expf(sg - mn);
      L = L * cw + pg;
      Aa.x = Aa.x * cw + pg * Vg[d0a + 0];
      Aa.y = Aa.y * cw + pg * Vg[d0a + 1];
      Aa.z = Aa.z * cw + pg * Vg[d0a + 2];
      Aa.w = Aa.w * cw + pg * Vg[d0a + 3];
      Ab.x = Ab.x * cw + pg * Vg[d0b + 0];
      Ab.y = Ab.y * cw + pg * Vg[d0b + 1];
      Ab.z = Ab.z * cw + pg * Vg[d0b + 2];
      Ab.w = Ab.w * cw + pg * Vg[d0b + 3];
      M = mn;
    }
  }

  const float inv = 1.f / L;
  float* orow = out + browoff * DD;
  *(float4*)&orow[d0a] = make_float4(Aa.x * inv, Aa.y * inv, Aa.z * inv, Aa.w * inv);
  *(float4*)&orow[d0b] = make_float4(Ab.x * inv, Ab.y * inv, Ab.z * inv, Ab.w * inv);
}

// ---------------------------------------------------------------------------
extern "C" void kernel_launch(void* const* d_in, const int* in_sizes, int n_in,
                              void* d_out, int out_size) {
  const float* q  = (const float*)d_in[0];
  const float* k  = (const float*)d_in[1];
  const float* v  = (const float*)d_in[2];
  const float* Wq = (const float*)d_in[3];
  const float* bq = (const float*)d_in[4];
  const float* Wk = (const float*)d_in[5];
  const float* bk = (const float*)d_in[6];
  const float* Wv = (const float*)d_in[7];
  const float* bv = (const float*)d_in[8];
  float* out = (float*)d_out;

  int gr[3], gc[3];
  compute_mask_pairs_h(gr, gc);

  const int ATTN_SMEM = 8 * TILEW * 4;  // 73,728 B
  cudaFuncSetAttribute(attn_split_kernel,
                       cudaFuncAttributeMaxDynamicSharedMemorySize, ATTN_SMEM);

  dim3 pg(128, 3);
  proj_kernel<<<pg, 128>>>(q, k, v, Wq, bq, Wk, bk, Wv, bv);
  attn_split_kernel<<<S_SPLIT * BATCH * (SEQ / 64), 128, ATTN_SMEM>>>();
  combine_kernel<<<BATCH * (SEQ / 8), 64>>>(out, gr[0], gc[0], gr[1], gc[1],
                                            gr[2], gc[2]);
}

// round 12
// speedup vs baseline: 1.1254x; 1.1254x over previous
#include <cuda_runtime.h>
#include <cuda_bf16.h>
#include <stdint.h>
#include <math.h>

#define BATCH 4
#define SEQ   2048
#define DIN   1024
#define DD    64
#define MTOT  (BATCH * SEQ)
#define S_SPLIT 4
#define NEGF  -1e30f

// ---------------------------------------------------------------------------
// Device scratch (no cudaMalloc allowed)
// ---------------------------------------------------------------------------
__device__ uint32_t g_hQ[MTOT * 32], g_lQ[MTOT * 32];
__device__ uint32_t g_hK[MTOT * 32], g_lK[MTOT * 32];
__device__ uint32_t g_hV[MTOT * 32], g_lV[MTOT * 32];
__device__ float g_pacc[S_SPLIT * MTOT * DD];
__device__ float g_pm[S_SPLIT * MTOT];
__device__ float g_pl[S_SPLIT * MTOT];

// ---------------------------------------------------------------------------
// Host-side replication of np.random.default_rng(0) mask-index generation
// ---------------------------------------------------------------------------
struct u128h { uint64_t hi, lo; };

static inline uint64_t mulhi64_h(uint64_t a, uint64_t b) {
  uint64_t al = (uint32_t)a, ah = a >> 32, bl = (uint32_t)b, bh = b >> 32;
  uint64_t p0 = al * bl, p1 = al * bh, p2 = ah * bl, p3 = ah * bh;
  uint64_t mid = (p0 >> 32) + (uint32_t)p1 + (uint32_t)p2;
  return p3 + (p1 >> 32) + (p2 >> 32) + (mid >> 32);
}

struct PCG64H {
  u128h state, inc;
  int has_uint32;
  uint32_t uinteger;
};

static inline void pcg_step_h(PCG64H* p) {
  const uint64_t mhi = 2549297995355413924ULL, mlo = 4865540595714422341ULL;
  u128h s = p->state, r;
  r.lo = s.lo * mlo;
  r.hi = mulhi64_h(s.lo, mlo) + s.lo * mhi + s.hi * mlo;
  uint64_t lo = r.lo + p->inc.lo;
  r.hi += p->inc.hi + (lo < r.lo);
  r.lo = lo;
  p->state = r;
}

static inline uint64_t rotr64_h(uint64_t v, unsigned r) {
  r &= 63u;
  return r ? ((v >> r) | (v << (64 - r))) : v;
}

static inline uint64_t pcg_next64_h(PCG64H* p) {
  pcg_step_h(p);
  return rotr64_h(p->state.hi ^ p->state.lo, (unsigned)(p->state.hi >> 58));
}

static inline uint32_t pcg_next32_h(PCG64H* p) {
  if (p->has_uint32) { p->has_uint32 = 0; return p->uinteger; }
  uint64_t n = pcg_next64_h(p);
  p->has_uint32 = 1;
  p->uinteger = (uint32_t)(n >> 32);
  return (uint32_t)n;
}

static void seedseq0_state_h(uint64_t out[4]) {
  const uint32_t INIT_A = 0x43b0d7e5u, MULT_A = 0x931e8875u;
  const uint32_t INIT_B = 0x8b51f9ddu, MULT_B = 0x58f38dedu;
  const uint32_t MIX_L = 0xca01f9ddu, MIX_R = 0x4973f715u;
  uint32_t pool[4];
  uint32_t hc = INIT_A;
  for (int i = 0; i < 4; i++) {
    uint32_t v = 0u;
    v ^= hc; hc *= MULT_A; v *= hc; v ^= v >> 16;
    pool[i] = v;
  }
  for (int s = 0; s < 4; s++) {
    for (int d = 0; d < 4; d++) {
      if (s == d) continue;
      uint32_t v = pool[s];
      v ^= hc; hc *= MULT_A; v *= hc; v ^= v >> 16;
      uint32_t r = (pool[d] * MIX_L) ^ (v * MIX_R);
      r ^= r >> 16;
      pool[d] = r;
    }
  }
  uint32_t hcb = INIT_B;
  uint32_t st[8];
  for (int i = 0; i < 8; i++) {
    uint32_t dv = pool[i & 3];
    dv ^= hcb; hcb *= MULT_B; dv *= hcb; dv ^= dv >> 16;
    st[i] = dv;
  }
  for (int k2 = 0; k2 < 4; k2++)
    out[k2] = (uint64_t)st[2 * k2] | ((uint64_t)st[2 * k2 + 1] << 32);
}

static inline uint64_t lemire32_h(PCG64H* p, uint32_t rng) {
  if (rng == 0) return 0;
  const uint32_t rng_excl = rng + 1;
  uint64_t m = (uint64_t)pcg_next32_h(p) * (uint64_t)rng_excl;
  uint32_t leftover = (uint32_t)m;
  if (leftover < rng_excl) {
    const uint32_t threshold = (uint32_t)(0xFFFFFFFFu - rng) % rng_excl;
    while (leftover < threshold) {
      m = (uint64_t)pcg_next32_h(p) * (uint64_t)rng_excl;
      leftover = (uint32_t)m;
    }
  }
  return m >> 32;
}

static void choice3_2048_h(PCG64H* p, int64_t idx[3]) {
  const int size = 3, pop = 2048;
  const uint64_t mask = 3;
  uint64_t hset[4] = {~0ull, ~0ull, ~0ull, ~0ull};
  for (int j = pop - size; j < pop; j++) {
    uint64_t val = lemire32_h(p, (uint32_t)j);
    uint64_t loc = val & mask;
    while (hset[loc] != ~0ull && hset[loc] != val) loc = (loc + 1) & mask;
    if (hset[loc] == ~0ull) {
      hset[loc] = val;
      idx[j - pop + size] = (int64_t)val;
    } else {
      loc = (uint64_t)j & mask;
      while (hset[loc] != ~0ull) loc = (loc + 1) & mask;
      hset[loc] = (uint64_t)j;
      idx[j - pop + size] = (int64_t)j;
    }
  }
  for (int i = size - 1; i >= 1; i--) {
    uint64_t jj = lemire32_h(p, (uint32_t)i);
    if ((int)jj != i) {
      int64_t t = idx[i]; idx[i] = idx[(int)jj]; idx[(int)jj] = t;
    }
  }
}

static void compute_mask_pairs_h(int gr[3], int gc[3]) {
  uint64_t sd[4];
  seedseq0_state_h(sd);
  PCG64H rng;
  rng.inc.hi = (sd[2] << 1) | (sd[3] >> 63);
  rng.inc.lo = (sd[3] << 1) | 1ull;
  rng.state.hi = 0; rng.state.lo = 0;
  pcg_step_h(&rng);
  uint64_t lo = rng.state.lo + sd[1];
  rng.state.hi += sd[0] + (lo < rng.state.lo);
  rng.state.lo = lo;
  pcg_step_h(&rng);
  rng.has_uint32 = 0; rng.uinteger = 0;

  int64_t rows[3], cols[3];
  choice3_2048_h(&rng, rows);
  choice3_2048_h(&rng, cols);
  for (int i = 0; i < 3; i++) { gr[i] = (int)rows[i]; gc[i] = (int)cols[i]; }
}

// ---------------------------------------------------------------------------
// helpers
// ---------------------------------------------------------------------------
__device__ __forceinline__ void split2(float x, float y, uint32_t& hi,
                                       uint32_t& lo) {
  float hx = __bfloat162float(__float2bfloat16(x));
  float hy = __bfloat162float(__float2bfloat16(y));
  __nv_bfloat162 h2 = __floats2bfloat162_rn(x, y);
  __nv_bfloat162 l2 = __floats2bfloat162_rn(x - hx, y - hy);
  hi = *reinterpret_cast<uint32_t*>(&h2);
  lo = *reinterpret_cast<uint32_t*>(&l2);
}

// reconstruct two floats from packed hi/lo bf16x2 words
__device__ __forceinline__ float2 join2(uint32_t h, uint32_t l) {
  __nv_bfloat162 hh = *reinterpret_cast<__nv_bfloat162*>(&h);
  __nv_bfloat162 ll = *reinterpret_cast<__nv_bfloat162*>(&l);
  return make_float2(__bfloat162float(hh.x) + __bfloat162float(ll.x),
                     __bfloat162float(hh.y) + __bfloat162float(ll.y));
}

__device__ __forceinline__ uint32_t smem_u32(const void* p) {
  return (uint32_t)__cvta_generic_to_shared(p);
}

__device__ __forceinline__ void cp_async16(uint32_t saddr, const void* g) {
  asm volatile("cp.async.cg.shared.global [%0], [%1], 16;" ::"r"(saddr),
               "l"(g));
}
__device__ __forceinline__ void cp_commit() {
  asm volatile("cp.async.commit_group;");
}
template <int N>
__device__ __forceinline__ void cp_wait() {
  asm volatile("cp.async.wait_group %0;" ::"n"(N));
}

__device__ __forceinline__ void ldsm_x4(uint32_t& r0, uint32_t& r1,
                                        uint32_t& r2, uint32_t& r3,
                                        uint32_t addr) {
  asm volatile(
      "ldmatrix.sync.aligned.m8n8.x4.shared.b16 {%0,%1,%2,%3}, [%4];"
      : "=r"(r0), "=r"(r1), "=r"(r2), "=r"(r3)
      : "r"(addr));
}

__device__ __forceinline__ void ldsm_x4_t(uint32_t& r0, uint32_t& r1,
                                          uint32_t& r2, uint32_t& r3,
                                          uint32_t addr) {
  asm volatile(
      "ldmatrix.sync.aligned.m8n8.x4.trans.shared.b16 {%0,%1,%2,%3}, [%4];"
      : "=r"(r0), "=r"(r1), "=r"(r2), "=r"(r3)
      : "r"(addr));
}

__device__ __forceinline__ void mma_bf16(float& d0, float& d1, float& d2,
                                         float& d3, uint32_t a0, uint32_t a1,
                                         uint32_t a2, uint32_t a3, uint32_t b0,
                                         uint32_t b1) {
  asm volatile(
      "mma.sync.aligned.m16n8k16.row.col.f32.bf16.bf16.f32 "
      "{%0,%1,%2,%3},{%4,%5,%6,%7},{%8,%9},{%0,%1,%2,%3};"
      : "+f"(d0), "+f"(d1), "+f"(d2), "+f"(d3)
      : "r"(a0), "r"(a1), "r"(a2), "r"(a3), "r"(b0), "r"(b1));
}

// ---------------------------------------------------------------------------
// Projection GEMM, 3xBF16 m16n8k16, register-prefetch staging (R8/R10 form).
// Epilogue writes ONLY the bf16 hi/lo planes (fp32 outputs unused downstream).
// ---------------------------------------------------------------------------
#define PSTR 20
#define WSTR 36

__global__ __launch_bounds__(128, 3) void proj_kernel(
    const float* __restrict__ in_q, const float* __restrict__ in_k,
    const float* __restrict__ in_v,
    const float* __restrict__ Wq, const float* __restrict__ bq,
    const float* __restrict__ Wk, const float* __restrict__ bk,
    const float* __restrict__ Wv, const float* __restrict__ bv) {
  const float* A; const float* W; const float* bias;
  uint32_t* hP; uint32_t* lP;
  int z = blockIdx.y;
  if (z == 0)      { A = in_q; W = Wq; bias = bq; hP = g_hQ; lP = g_lQ; }
  else if (z == 1) { A = in_k; W = Wk; bias = bk; hP = g_hK; lP = g_lK; }
  else             { A = in_v; W = Wv; bias = bv; hP = g_hV; lP = g_lV; }

  __shared__ uint32_t Ah[64 * PSTR], Al[64 * PSTR];
  __shared__ uint32_t Wh[32 * WSTR], Wl[32 * WSTR];

  const int t = threadIdx.x;
  const int w = t >> 5;
  const int lane = t & 31;
  const int g = lane >> 2;
  const int tig = lane & 3;
  const int m0 = blockIdx.x * 64;
  const int mw = w * 16;

  float acc[8][4];
#pragma unroll
  for (int nb = 0; nb < 8; nb++)
#pragma unroll
    for (int i = 0; i < 4; i++) acc[nb][i] = 0.f;

  float4 arg[4], wrg[4];
#pragma unroll
  for (int i = 0; i < 4; i++) {
    int fidx = t + i * 128;
    arg[i] = *(const float4*)&A[(size_t)(m0 + (fidx >> 3)) * DIN +
                                (fidx & 7) * 4];
    wrg[i] = *(const float4*)&W[(size_t)(fidx >> 4) * DD + (fidx & 15) * 4];
  }

  for (int k0 = 0; k0 < DIN; k0 += 32) {
#pragma unroll
    for (int i = 0; i < 4; i++) {
      int fidx = t + i * 128;
      {
        int row = fidx >> 3, c = fidx & 7;
        float4 v = arg[i];
        uint32_t h0, l0, h1, l1;
        split2(v.x, v.y, h0, l0);
        split2(v.z, v.w, h1, l1);
        *(uint2*)&Ah[row * PSTR + 2 * c] = make_uint2(h0, h1);
        *(uint2*)&Al[row * PSTR + 2 * c] = make_uint2(l0, l1);
      }
      {
        int krow = fidx >> 4, c4 = fidx & 15;
        float4 v = wrg[i];
        uint32_t h0, l0, h1, l1;
        split2(v.x, v.y, h0, l0);
        split2(v.z, v.w, h1, l1);
        *(uint2*)&Wh[krow * WSTR + 2 * c4] = make_uint2(h0, h1);
        *(uint2*)&Wl[krow * WSTR + 2 * c4] = make_uint2(l0, l1);
      }
    }
    __syncthreads();

    if (k0 + 32 < DIN) {
#pragma unroll
      for (int i = 0; i < 4; i++) {
        int fidx = t + i * 128;
        arg[i] = *(const float4*)&A[(size_t)(m0 + (fidx >> 3)) * DIN + k0 +
                                    32 + (fidx & 7) * 4];
        wrg[i] = *(const float4*)&W[(size_t)(k0 + 32 + (fidx >> 4)) * DD +
                                    (fidx & 15) * 4];
      }
    }

#pragma unroll
    for (int ks = 0; ks < 2; ks++) {
      int arow = mw + ((lane >> 3) & 1) * 8 + (lane & 7);
      int acol = ks * 8 + (lane >> 4) * 4;
      uint32_t ah0, ah1, ah2, ah3, al0, al1, al2, al3;
      ldsm_x4(ah0, ah1, ah2, ah3, smem_u32(&Ah[arow * PSTR + acol]));
      ldsm_x4(al0, al1, al2, al3, smem_u32(&Al[arow * PSTR + acol]));
#pragma unroll
      for (int nbp = 0; nbp < 4; nbp++) {
        int wk = ks * 16 + ((lane >> 3) & 1) * 8 + (lane & 7);
        int wnp = nbp * 8 + (lane >> 4) * 4;
        uint32_t bh0, bh1, bh2, bh3, bl0, bl1, bl2, bl3;
        ldsm_x4_t(bh0, bh1, bh2, bh3, smem_u32(&Wh[wk * WSTR + wnp]));
        ldsm_x4_t(bl0, bl1, bl2, bl3, smem_u32(&Wl[wk * WSTR + wnp]));
        int n0 = 2 * nbp, n1 = n0 + 1;
        mma_bf16(acc[n0][0], acc[n0][1], acc[n0][2], acc[n0][3],
                 ah0, ah1, ah2, ah3, bh0, bh1);
        mma_bf16(acc[n1][0], acc[n1][1], acc[n1][2], acc[n1][3],
                 ah0, ah1, ah2, ah3, bh2, bh3);
        mma_bf16(acc[n0][0], acc[n0][1], acc[n0][2], acc[n0][3],
                 al0, al1, al2, al3, bh0, bh1);
        mma_bf16(acc[n1][0], acc[n1][1], acc[n1][2], acc[n1][3],
                 al0, al1, al2, al3, bh2, bh3);
        mma_bf16(acc[n0][0], acc[n0][1], acc[n0][2], acc[n0][3],
                 ah0, ah1, ah2, ah3, bl0, bl1);
        mma_bf16(acc[n1][0], acc[n1][1], acc[n1][2], acc[n1][3],
                 ah0, ah1, ah2, ah3, bl2, bl3);
      }
    }
    __syncthreads();
  }

#pragma unroll
  for (int nb = 0; nb < 8; nb++) {
    int n = nb * 8 + tig * 2;
    float b0v = bias[n], b1v = bias[n + 1];
    float2 o0 = make_float2(acc[nb][0] + b0v, acc[nb][1] + b1v);
    float2 o1 = make_float2(acc[nb][2] + b0v, acc[nb][3] + b1v);
    size_t row0 = (size_t)(m0 + mw + g);
    size_t row1 = row0 + 8;
    uint32_t h, l;
    split2(o0.x, o0.y, h, l);
    hP[row0 * 32 + nb * 4 + tig] = h;
    lP[row0 * 32 + nb * 4 + tig] = l;
    split2(o1.x, o1.y, h, l);
    hP[row1 * 32 + nb * 4 + tig] = h;
    lP[row1 * 32 + nb * 4 + tig] = l;
  }
}

// ---------------------------------------------------------------------------
// Flash attention, 3xBF16 m16n8k16, split-K x4, cp.async plane staging,
// double-buffered. (R10, unchanged)
// ---------------------------------------------------------------------------
#define KSTR 36
#define TILEW (64 * KSTR)

__global__ __launch_bounds__(128, 3) void attn_split_kernel() {
  extern __shared__ uint32_t sm[];
  uint32_t* KhB = sm;
  uint32_t* KlB = sm + 2 * TILEW;
  uint32_t* VhB = sm + 4 * TILEW;
  uint32_t* VlB = sm + 6 * TILEW;

  const int bid = blockIdx.x;
  const int s = bid >> 7;
  const int rest = bid & 127;
  const int b = rest >> 5;
  const int qt = rest & 31;
  const int qr0 = qt * 64;
  const int T = qt + 1;
  const int t0 = (s * T) / S_SPLIT;
  const int t1 = ((s + 1) * T) / S_SPLIT;

  const int t = threadIdx.x;
  const int w = t >> 5;
  const int lane = t & 31;
  const int g = lane >> 2;
  const int tig = lane & 3;
  const int mw = w * 16;

  const size_t pbase = ((size_t)s * BATCH + b) * SEQ + qr0;

  if (t0 == t1) {
    for (int i = t; i < 64 * 16; i += 128) {
      int row = i >> 4, c4 = (i & 15) * 4;
      *(float4*)&g_pacc[(pbase + row) * DD + c4] =
          make_float4(0.f, 0.f, 0.f, 0.f);
    }
    if (t < 64) { g_pm[pbase + t] = NEGF; g_pl[pbase + t] = 0.f; }
    return;
  }

  const uint32_t* __restrict__ pQh = g_hQ + (size_t)b * SEQ * 32;
  const uint32_t* __restrict__ pQl = g_lQ + (size_t)b * SEQ * 32;
  const uint32_t* __restrict__ pKh = g_hK + (size_t)b * SEQ * 32;
  const uint32_t* __restrict__ pKl = g_lK + (size_t)b * SEQ * 32;
  const uint32_t* __restrict__ pVh = g_hV + (size_t)b * SEQ * 32;
  const uint32_t* __restrict__ pVl = g_lV + (size_t)b * SEQ * 32;

#pragma unroll
  for (int i = 0; i < 4; i++) {
    int idx = t + i * 128;
    int row = idx >> 3, j4 = idx & 7;
    cp_async16(smem_u32(&KhB[row * KSTR + 4 * j4]),
               &pQh[(size_t)(qr0 + row) * 32 + 4 * j4]);
    cp_async16(smem_u32(&KlB[row * KSTR + 4 * j4]),
               &pQl[(size_t)(qr0 + row) * 32 + 4 * j4]);
  }
  cp_commit();
  cp_wait<0>();
  __syncthreads();

  uint32_t qh[4][4], ql[4][4];
#pragma unroll
  for (int ks = 0; ks < 4; ks++) {
    int arow = mw + ((lane >> 3) & 1) * 8 + (lane & 7);
    int acol = ks * 8 + (lane >> 4) * 4;
    ldsm_x4(qh[ks][0], qh[ks][1], qh[ks][2], qh[ks][3],
            smem_u32(&KhB[arow * KSTR + acol]));
    ldsm_x4(ql[ks][0], ql[ks][1], ql[ks][2], ql[ks][3],
            smem_u32(&KlB[arow * KSTR + acol]));
  }
  __syncthreads();

  {
    int j0 = t0 * 64;
#pragma unroll
    for (int i = 0; i < 4; i++) {
      int idx = t + i * 128;
      int row = idx >> 3, j4 = idx & 7;
      size_t goff = (size_t)(j0 + row) * 32 + 4 * j4;
      uint32_t soff = row * KSTR + 4 * j4;
      cp_async16(smem_u32(&KhB[soff]), &pKh[goff]);
      cp_async16(smem_u32(&KlB[soff]), &pKl[goff]);
      cp_async16(smem_u32(&VhB[soff]), &pVh[goff]);
      cp_async16(smem_u32(&VlB[soff]), &pVl[goff]);
    }
    cp_commit();
  }

  float m0 = NEGF, m1 = NEGF, l0s = 0.f, l1s = 0.f;
  float acc[8][4];
#pragma unroll
  for (int nb = 0; nb < 8; nb++)
#pragma unroll
    for (int i = 0; i < 4; i++) acc[nb][i] = 0.f;

  const int row0g = qr0 + mw + g;
  const int row1g = row0g + 8;

  for (int kt = t0; kt < t1; kt++) {
    const int it = kt - t0;
    const int p = it & 1;
    cp_wait<0>();
    __syncthreads();

    if (kt + 1 < t1) {
      int j0n = (kt + 1) * 64;
      uint32_t bofs = (p ^ 1) * TILEW;
#pragma unroll
      for (int i = 0; i < 4; i++) {
        int idx = t + i * 128;
        int row = idx >> 3, j4 = idx & 7;
        size_t goff = (size_t)(j0n + row) * 32 + 4 * j4;
        uint32_t soff = bofs + row * KSTR + 4 * j4;
        cp_async16(smem_u32(&KhB[soff]), &pKh[goff]);
        cp_async16(smem_u32(&KlB[soff]), &pKl[goff]);
        cp_async16(smem_u32(&VhB[soff]), &pVh[goff]);
        cp_async16(smem_u32(&VlB[soff]), &pVl[goff]);
      }
      cp_commit();
    }

    const uint32_t* KhT = KhB + p * TILEW;
    const uint32_t* KlT = KlB + p * TILEW;
    const uint32_t* VhT = VhB + p * TILEW;
    const uint32_t* VlT = VlB + p * TILEW;
    const int j0 = kt * 64;

    float sacc[8][4];
#pragma unroll
    for (int nb = 0; nb < 8; nb++)
#pragma unroll
      for (int i = 0; i < 4; i++) sacc[nb][i] = 0.f;
#pragma unroll
    for (int ks = 0; ks < 4; ks++) {
#pragma unroll
      for (int nbp = 0; nbp < 4; nbp++) {
        int krow = nbp * 16 + (lane >> 4) * 8 + (lane & 7);
        int kcol = ks * 8 + ((lane >> 3) & 1) * 4;
        uint32_t bh0, bh1, bh2, bh3, bl0, bl1, bl2, bl3;
        ldsm_x4(bh0, bh1, bh2, bh3, smem_u32(&KhT[krow * KSTR + kcol]));
        ldsm_x4(bl0, bl1, bl2, bl3, smem_u32(&KlT[krow * KSTR + kcol]));
        int n0 = 2 * nbp, n1 = n0 + 1;
        mma_bf16(sacc[n0][0], sacc[n0][1], sacc[n0][2], sacc[n0][3],
                 qh[ks][0], qh[ks][1], qh[ks][2], qh[ks][3], bh0, bh1);
        mma_bf16(sacc[n1][0], sacc[n1][1], sacc[n1][2], sacc[n1][3],
                 qh[ks][0], qh[ks][1], qh[ks][2], qh[ks][3], bh2, bh3);
        mma_bf16(sacc[n0][0], sacc[n0][1], sacc[n0][2], sacc[n0][3],
                 ql[ks][0], ql[ks][1], ql[ks][2], ql[ks][3], bh0, bh1);
        mma_bf16(sacc[n1][0], sacc[n1][1], sacc[n1][2], sacc[n1][3],
                 ql[ks][0], ql[ks][1], ql[ks][2], ql[ks][3], bh2, bh3);
        mma_bf16(sacc[n0][0], sacc[n0][1], sacc[n0][2], sacc[n0][3],
                 qh[ks][0], qh[ks][1], qh[ks][2], qh[ks][3], bl0, bl1);
        mma_bf16(sacc[n1][0], sacc[n1][1], sacc[n1][2], sacc[n1][3],
                 qh[ks][0], qh[ks][1], qh[ks][2], qh[ks][3], bl2, bl3);
      }
    }

#pragma unroll
    for (int nb = 0; nb < 8; nb++) {
      sacc[nb][0] *= 0.125f; sacc[nb][1] *= 0.125f;
      sacc[nb][2] *= 0.125f; sacc[nb][3] *= 0.125f;
    }

    if (kt == T - 1) {
#pragma unroll
      for (int nb = 0; nb < 8; nb++) {
        int kg = j0 + nb * 8 + tig * 2;
        if (kg > row0g)     sacc[nb][0] = NEGF;
        if (kg + 1 > row0g) sacc[nb][1] = NEGF;
        if (kg > row1g)     sacc[nb][2] = NEGF;
        if (kg + 1 > row1g) sacc[nb][3] = NEGF;
      }
    }

    float mx0 = NEGF, mx1 = NEGF;
#pragma unroll
    for (int nb = 0; nb < 8; nb++) {
      mx0 = fmaxf(mx0, fmaxf(sacc[nb][0], sacc[nb][1]));
      mx1 = fmaxf(mx1, fmaxf(sacc[nb][2], sacc[nb][3]));
    }
    mx0 = fmaxf(mx0, __shfl_xor_sync(0xffffffffu, mx0, 1));
    mx0 = fmaxf(mx0, __shfl_xor_sync(0xffffffffu, mx0, 2));
    mx1 = fmaxf(mx1, __shfl_xor_sync(0xffffffffu, mx1, 1));
    mx1 = fmaxf(mx1, __shfl_xor_sync(0xffffffffu, mx1, 2));
    const float mn0 = fmaxf(m0, mx0);
    const float mn1 = fmaxf(m1, mx1);
    const float c0 = __expf(m0 - mn0);
    const float c1 = __expf(m1 - mn1);

    uint32_t pha[8], phb[8], pla[8], plb[8];
    float s0 = 0.f, s1 = 0.f;
#pragma unroll
    for (int nb = 0; nb < 8; nb++) {
      float p00 = __expf(sacc[nb][0] - mn0);
      float p01 = __expf(sacc[nb][1] - mn0);
      float p10 = __expf(sacc[nb][2] - mn1);
      float p11 = __expf(sacc[nb][3] - mn1);
      s0 += p00 + p01;
      s1 += p10 + p11;
      split2(p00, p01, pha[nb], pla[nb]);
      split2(p10, p11, phb[nb], plb[nb]);
    }
    s0 += __shfl_xor_sync(0xffffffffu, s0, 1);
    s0 += __shfl_xor_sync(0xffffffffu, s0, 2);
    s1 += __shfl_xor_sync(0xffffffffu, s1, 1);
    s1 += __shfl_xor_sync(0xffffffffu, s1, 2);
    l0s = l0s * c0 + s0;
    l1s = l1s * c1 + s1;
    m0 = mn0;
    m1 = mn1;
#pragma unroll
    for (int nb = 0; nb < 8; nb++) {
      acc[nb][0] *= c0; acc[nb][1] *= c0;
      acc[nb][2] *= c1; acc[nb][3] *= c1;
    }

#pragma unroll
    for (int kb = 0; kb < 4; kb++) {
      uint32_t a0h = pha[2 * kb], a1h = phb[2 * kb];
      uint32_t a2h = pha[2 * kb + 1], a3h = phb[2 * kb + 1];
      uint32_t a0l = pla[2 * kb], a1l = plb[2 * kb];
      uint32_t a2l = pla[2 * kb + 1], a3l = plb[2 * kb + 1];
#pragma unroll
      for (int nbp = 0; nbp < 4; nbp++) {
        int vkey = kb * 16 + ((lane >> 3) & 1) * 8 + (lane & 7);
        int vdp = nbp * 8 + (lane >> 4) * 4;
        uint32_t bh0, bh1, bh2, bh3, bl0, bl1, bl2, bl3;
        ldsm_x4_t(bh0, bh1, bh2, bh3, smem_u32(&VhT[vkey * KSTR + vdp]));
        ldsm_x4_t(bl0, bl1, bl2, bl3, smem_u32(&VlT[vkey * KSTR + vdp]));
        int n0 = 2 * nbp, n1 = n0 + 1;
        mma_bf16(acc[n0][0], acc[n0][1], acc[n0][2], acc[n0][3],
                 a0h, a1h, a2h, a3h, bh0, bh1);
        mma_bf16(acc[n1][0], acc[n1][1], acc[n1][2], acc[n1][3],
                 a0h, a1h, a2h, a3h, bh2, bh3);
        mma_bf16(acc[n0][0], acc[n0][1], acc[n0][2], acc[n0][3],
                 a0l, a1l, a2l, a3l, bh0, bh1);
        mma_bf16(acc[n1][0], acc[n1][1], acc[n1][2], acc[n1][3],
                 a0l, a1l, a2l, a3l, bh2, bh3);
        mma_bf16(acc[n0][0], acc[n0][1], acc[n0][2], acc[n0][3],
                 a0h, a1h, a2h, a3h, bl0, bl1);
        mma_bf16(acc[n1][0], acc[n1][1], acc[n1][2], acc[n1][3],
                 a0h, a1h, a2h, a3h, bl2, bl3);
      }
    }
  }

  const size_t r0 = pbase + mw + g;
  const size_t r1 = r0 + 8;
  if (tig == 0) {
    g_pm[r0] = m0; g_pl[r0] = l0s;
    g_pm[r1] = m1; g_pl[r1] = l1s;
  }
#pragma unroll
  for (int nb = 0; nb < 8; nb++) {
    int n = nb * 8 + tig * 2;
    *(float2*)&g_pacc[r0 * DD + n] = make_float2(acc[nb][0], acc[nb][1]);
    *(float2*)&g_pacc[r1 * DD + n] = make_float2(acc[nb][2], acc[nb][3]);
  }
}

// ---------------------------------------------------------------------------
// Combine: 1024 blocks x 64 threads (8 rows/block). Global-token corrections
// reconstruct Q/K/V from the bf16 hi/lo planes.
// ---------------------------------------------------------------------------
__global__ __launch_bounds__(64) void combine_kernel(
    float* __restrict__ out,
    int gr0, int gc0, int gr1, int gc1, int gr2, int gc2) {
  const int bid = blockIdx.x;
  const int b = bid >> 8;
  const int rt = bid & 255;
  const int t = threadIdx.x;
  const int r = t >> 3;
  const int sub = t & 7;
  const int row = rt * 8 + r;
  const int d0a = sub * 4;
  const int d0b = 32 + sub * 4;
  const size_t browoff = (size_t)b * SEQ + row;

  float ms[S_SPLIT], ls[S_SPLIT];
  float M = NEGF;
#pragma unroll
  for (int s = 0; s < S_SPLIT; s++) {
    size_t prow = ((size_t)s * BATCH + b) * SEQ + row;
    ms[s] = g_pm[prow];
    ls[s] = g_pl[prow];
    M = fmaxf(M, ms[s]);
  }
  float L = 0.f;
  float4 Aa = make_float4(0.f, 0.f, 0.f, 0.f);
  float4 Ab = make_float4(0.f, 0.f, 0.f, 0.f);
#pragma unroll
  for (int s = 0; s < S_SPLIT; s++) {
    size_t prow = ((size_t)s * BATCH + b) * SEQ + row;
    float w = __expf(ms[s] - M);
    L += ls[s] * w;
    const float* pr = g_pacc + prow * DD;
    float4 pa = *(const float4*)&pr[d0a];
    float4 pb = *(const float4*)&pr[d0b];
    Aa.x += w * pa.x; Aa.y += w * pa.y; Aa.z += w * pa.z; Aa.w += w * pa.w;
    Ab.x += w * pb.x; Ab.y += w * pb.y; Ab.z += w * pb.z; Ab.w += w * pb.w;
  }

  const int grs[3] = {gr0, gr1, gr2};
  const int gcs[3] = {gc0, gc1, gc2};
  // plane word indices for this thread's 8 dims: {2sub, 2sub+1, 16+2sub, 17+2sub}
  const int wa0 = 2 * sub, wb0 = 16 + 2 * sub;
#pragma unroll
  for (int g = 0; g < 3; g++) {
    int grr = grs[g], gcc = gcs[g];
    if (row == grr && gcc > grr) {
      size_t qoff = browoff * 32;
      size_t koff = ((size_t)b * SEQ + gcc) * 32;
      float2 q0 = join2(g_hQ[qoff + wa0], g_lQ[qoff + wa0]);
      float2 q1 = join2(g_hQ[qoff + wa0 + 1], g_lQ[qoff + wa0 + 1]);
      float2 q2 = join2(g_hQ[qoff + wb0], g_lQ[qoff + wb0]);
      float2 q3 = join2(g_hQ[qoff + wb0 + 1], g_lQ[qoff + wb0 + 1]);
      float2 k0 = join2(g_hK[koff + wa0], g_lK[koff + wa0]);
      float2 k1 = join2(g_hK[koff + wa0 + 1], g_lK[koff + wa0 + 1]);
      float2 k2 = join2(g_hK[koff + wb0], g_lK[koff + wb0]);
      float2 k3 = join2(g_hK[koff + wb0 + 1], g_lK[koff + wb0 + 1]);
      float part = q0.x * k0.x + q0.y * k0.y + q1.x * k1.x + q1.y * k1.y +
                   q2.x * k2.x + q2.y * k2.y + q3.x * k3.x + q3.y * k3.y;
      part += __shfl_xor_sync(0xffffffffu, part, 1);
      part += __shfl_xor_sync(0xffffffffu, part, 2);
      part += __shfl_xor_sync(0xffffffffu, part, 4);
      float sg = part * 0.125f;
      float mn = fmaxf(M, sg);
      float cw = __expf(M - mn);
      float pg = __expf(sg - mn);
      L = L * cw + pg;
      float2 v0 = join2(g_hV[koff + wa0], g_lV[koff + wa0]);
      float2 v1 = join2(g_hV[koff + wa0 + 1], g_lV[koff + wa0 + 1]);
      float2 v2 = join2(g_hV[koff + wb0], g_lV[koff + wb0]);
      float2 v3 = join2(g_hV[koff + wb0 + 1], g_lV[koff + wb0 + 1]);
      Aa.x = Aa.x * cw + pg * v0.x;
      Aa.y = Aa.y * cw + pg * v0.y;
      Aa.z = Aa.z * cw + pg * v1.x;
      Aa.w = Aa.w * cw + pg * v1.y;
      Ab.x = Ab.x * cw + pg * v2.x;
      Ab.y = Ab.y * cw + pg * v2.y;
      Ab.z = Ab.z * cw + pg * v3.x;
      Ab.w = Ab.w * cw + pg * v3.y;
      M = mn;
    }
  }

  const float inv = 1.f / L;
  float* orow = out + browoff * DD;
  *(float4*)&orow[d0a] = make_float4(Aa.x * inv, Aa.y * inv, Aa.z * inv, Aa.w * inv);
  *(float4*)&orow[d0b] = make_float4(Ab.x * inv, Ab.y * inv, Ab.z * inv, Ab.w * inv);
}

// ---------------------------------------------------------------------------
extern "C" void kernel_launch(void* const* d_in, const int* in_sizes, int n_in,
                              void* d_out, int out_size) {
  const float* q  = (const float*)d_in[0];
  const float* k  = (const float*)d_in[1];
  const float* v  = (const float*)d_in[2];
  const float* Wq = (const float*)d_in[3];
  const float* bq = (const float*)d_in[4];
  const float* Wk = (const float*)d_in[5];
  const float* bk = (const float*)d_in[6];
  const float* Wv = (const float*)d_in[7];
  const float* bv = (const float*)d_in[8];
  float* out = (float*)d_out;

  int gr[3], gc[3];
  compute_mask_pairs_h(gr, gc);

  const int ATTN_SMEM = 8 * TILEW * 4;  // 73,728 B
  cudaFuncSetAttribute(attn_split_kernel,
                       cudaFuncAttributeMaxDynamicSharedMemorySize, ATTN_SMEM);

  dim3 pg(128, 3);
  proj_kernel<<<pg, 128>>>(q, k, v, Wq, bq, Wk, bk, Wv, bv);
  attn_split_kernel<<<S_SPLIT * BATCH * (SEQ / 64), 128, ATTN_SMEM>>>();
  combine_kernel<<<BATCH * (SEQ / 8), 64>>>(out, gr[0], gc[0], gr[1], gc[1],
                                            gr[2], gc[2]);
}